// round 1
// baseline (speedup 1.0000x reference)
#include <cuda_runtime.h>
#include <math.h>

#define BB 16
#define KK 1024
#define NN 4096
#define DD 512

// 268 MB scratch for scores/attention matrix (allowed: __device__ global array)
__device__ float g_scores[(size_t)BB * KK * NN];

// ---------------- FMA-only exp (avoids MUFU bottleneck: 67M exps) -------------
__device__ __forceinline__ float fast_exp(float x) {
    // valid for x <= 0 (softmax shifted); clamp to avoid denormal/overflow issues
    x = fmaxf(x, -87.0f);
    float t = x * 1.4426950408889634f;     // x * log2(e)
    float n = rintf(t);
    // Cody-Waite: r = x - n*ln2
    float r = fmaf(n, -0.693145751953125f, x);
    r = fmaf(n, -1.428606765330187e-06f, r);
    // degree-6 Taylor of e^r on [-0.347, 0.347]: rel err ~1e-7
    float p = 1.38888892e-3f;
    p = fmaf(p, r, 8.33333377e-3f);
    p = fmaf(p, r, 4.16666679e-2f);
    p = fmaf(p, r, 1.66666672e-1f);
    p = fmaf(p, r, 0.5f);
    p = fmaf(p, r, 1.0f);
    p = fmaf(p, r, 1.0f);
    float s = __int_as_float(((int)n + 127) << 23);  // 2^n
    return p * s;
}

// ---------------- Kernel 1: scores[b,k,n] = sum_d cb[b,k,d]*pe[b,n,d] ---------
// SGEMM-NT: both operands D(=K-dim)-contiguous. 128x128 tile, BK=16, 8x8 micro.
__global__ __launch_bounds__(256, 2)
void qk_kernel(const float* __restrict__ cb, const float* __restrict__ pe)
{
    const int b = blockIdx.z;
    const float* A  = cb + (size_t)b * KK * DD;
    const float* Bp = pe + (size_t)b * NN * DD;
    float* C = g_scores + (size_t)b * KK * NN;
    const int m0 = blockIdx.y * 128;
    const int n0 = blockIdx.x * 128;

    __shared__ float As[2][16][128];
    __shared__ float Bs[2][16][128];

    const int tid = threadIdx.x;
    const int tx = tid & 15;
    const int ty = tid >> 4;

    const int lrow0 = tid >> 2;          // 0..63 (second half +64)
    const int lc4   = (tid & 3) << 2;    // 0,4,8,12

    float acc[8][8];
    #pragma unroll
    for (int i = 0; i < 8; i++)
        #pragma unroll
        for (int j = 0; j < 8; j++) acc[i][j] = 0.f;

    float4 ra[2], rb[2];

    // prologue: stage 0
    #pragma unroll
    for (int u = 0; u < 2; u++) {
        int row = lrow0 + u * 64;
        ra[u] = *reinterpret_cast<const float4*>(A  + (size_t)(m0 + row) * DD + lc4);
        rb[u] = *reinterpret_cast<const float4*>(Bp + (size_t)(n0 + row) * DD + lc4);
    }
    #pragma unroll
    for (int u = 0; u < 2; u++) {
        int row = lrow0 + u * 64;
        As[0][lc4 + 0][row] = ra[u].x; As[0][lc4 + 1][row] = ra[u].y;
        As[0][lc4 + 2][row] = ra[u].z; As[0][lc4 + 3][row] = ra[u].w;
        Bs[0][lc4 + 0][row] = rb[u].x; Bs[0][lc4 + 1][row] = rb[u].y;
        Bs[0][lc4 + 2][row] = rb[u].z; Bs[0][lc4 + 3][row] = rb[u].w;
    }
    __syncthreads();

    int buf = 0;
    #pragma unroll 1
    for (int kt = 0; kt < DD / 16; kt++) {
        if (kt + 1 < DD / 16) {
            const int koff = (kt + 1) * 16 + lc4;
            #pragma unroll
            for (int u = 0; u < 2; u++) {
                int row = lrow0 + u * 64;
                ra[u] = *reinterpret_cast<const float4*>(A  + (size_t)(m0 + row) * DD + koff);
                rb[u] = *reinterpret_cast<const float4*>(Bp + (size_t)(n0 + row) * DD + koff);
            }
        }
        #pragma unroll
        for (int k = 0; k < 16; k++) {
            float4 a0 = *reinterpret_cast<const float4*>(&As[buf][k][ty * 8]);
            float4 a1 = *reinterpret_cast<const float4*>(&As[buf][k][ty * 8 + 4]);
            float4 b0 = *reinterpret_cast<const float4*>(&Bs[buf][k][tx * 8]);
            float4 b1 = *reinterpret_cast<const float4*>(&Bs[buf][k][tx * 8 + 4]);
            float av[8] = {a0.x, a0.y, a0.z, a0.w, a1.x, a1.y, a1.z, a1.w};
            float bv[8] = {b0.x, b0.y, b0.z, b0.w, b1.x, b1.y, b1.z, b1.w};
            #pragma unroll
            for (int i = 0; i < 8; i++)
                #pragma unroll
                for (int j = 0; j < 8; j++)
                    acc[i][j] = fmaf(av[i], bv[j], acc[i][j]);
        }
        if (kt + 1 < DD / 16) {
            int nb = buf ^ 1;
            #pragma unroll
            for (int u = 0; u < 2; u++) {
                int row = lrow0 + u * 64;
                As[nb][lc4 + 0][row] = ra[u].x; As[nb][lc4 + 1][row] = ra[u].y;
                As[nb][lc4 + 2][row] = ra[u].z; As[nb][lc4 + 3][row] = ra[u].w;
                Bs[nb][lc4 + 0][row] = rb[u].x; Bs[nb][lc4 + 1][row] = rb[u].y;
                Bs[nb][lc4 + 2][row] = rb[u].z; Bs[nb][lc4 + 3][row] = rb[u].w;
            }
            __syncthreads();
            buf = nb;
        }
    }

    #pragma unroll
    for (int i = 0; i < 8; i++) {
        float4 o0 = make_float4(acc[i][0], acc[i][1], acc[i][2], acc[i][3]);
        float4 o1 = make_float4(acc[i][4], acc[i][5], acc[i][6], acc[i][7]);
        float* cp = C + (size_t)(m0 + ty * 8 + i) * NN + n0 + tx * 8;
        *reinterpret_cast<float4*>(cp)     = o0;
        *reinterpret_cast<float4*>(cp + 4) = o1;
    }
}

// ---------------- Kernel 2: in-place row softmax over N=4096 ------------------
__global__ __launch_bounds__(256)
void softmax_kernel()
{
    float* p = g_scores + (size_t)blockIdx.x * NN;
    const int tid = threadIdx.x;
    __shared__ float red[8];

    float4 v[4];
    float m = -3.4e38f;
    #pragma unroll
    for (int i = 0; i < 4; i++) {
        v[i] = reinterpret_cast<float4*>(p)[tid + i * 256];
        m = fmaxf(m, fmaxf(fmaxf(v[i].x, v[i].y), fmaxf(v[i].z, v[i].w)));
    }
    #pragma unroll
    for (int o = 16; o > 0; o >>= 1) m = fmaxf(m, __shfl_xor_sync(0xffffffffu, m, o));
    if ((tid & 31) == 0) red[tid >> 5] = m;
    __syncthreads();
    m = red[0];
    #pragma unroll
    for (int w = 1; w < 8; w++) m = fmaxf(m, red[w]);
    __syncthreads();

    float s = 0.f;
    #pragma unroll
    for (int i = 0; i < 4; i++) {
        v[i].x = fast_exp(v[i].x - m);
        v[i].y = fast_exp(v[i].y - m);
        v[i].z = fast_exp(v[i].z - m);
        v[i].w = fast_exp(v[i].w - m);
        s += (v[i].x + v[i].y) + (v[i].z + v[i].w);
    }
    #pragma unroll
    for (int o = 16; o > 0; o >>= 1) s += __shfl_xor_sync(0xffffffffu, s, o);
    if ((tid & 31) == 0) red[tid >> 5] = s;
    __syncthreads();
    s = ((red[0] + red[1]) + (red[2] + red[3])) + ((red[4] + red[5]) + (red[6] + red[7]));

    const float inv = 1.0f / s;
    #pragma unroll
    for (int i = 0; i < 4; i++) {
        v[i].x *= inv; v[i].y *= inv; v[i].z *= inv; v[i].w *= inv;
        reinterpret_cast<float4*>(p)[tid + i * 256] = v[i];
    }
}

// ---------------- Kernel 3: out[b,k,d] = sum_n P[b,k,n]*pe[b,n,d] -------------
// SGEMM-NN: A (attn) K-contiguous, B (patch) N-contiguous.
__global__ __launch_bounds__(256, 2)
void pv_kernel(const float* __restrict__ pe, float* __restrict__ outp)
{
    const int b = blockIdx.z;
    const float* A  = g_scores + (size_t)b * KK * NN;
    const float* Bp = pe + (size_t)b * NN * DD;
    float* C = outp + (size_t)b * KK * DD;
    const int m0 = blockIdx.y * 128;
    const int n0 = blockIdx.x * 128;  // over D

    __shared__ float As[2][16][128];
    __shared__ float Bs[2][16][128];

    const int tid = threadIdx.x;
    const int tx = tid & 15;
    const int ty = tid >> 4;

    const int lrow0 = tid >> 2;          // A-loader: 0..63 (+64)
    const int lc4   = (tid & 3) << 2;
    const int br0 = tid >> 5;            // B-loader rows: 0..7 (+8)
    const int bc  = (tid & 31) << 2;     // 0..124

    float acc[8][8];
    #pragma unroll
    for (int i = 0; i < 8; i++)
        #pragma unroll
        for (int j = 0; j < 8; j++) acc[i][j] = 0.f;

    float4 ra[2], rb[2];

    #pragma unroll
    for (int u = 0; u < 2; u++) {
        int row = lrow0 + u * 64;
        ra[u] = *reinterpret_cast<const float4*>(A + (size_t)(m0 + row) * NN + lc4);
        int brow = br0 + u * 8;
        rb[u] = *reinterpret_cast<const float4*>(Bp + (size_t)brow * DD + n0 + bc);
    }
    #pragma unroll
    for (int u = 0; u < 2; u++) {
        int row = lrow0 + u * 64;
        As[0][lc4 + 0][row] = ra[u].x; As[0][lc4 + 1][row] = ra[u].y;
        As[0][lc4 + 2][row] = ra[u].z; As[0][lc4 + 3][row] = ra[u].w;
        int brow = br0 + u * 8;
        *reinterpret_cast<float4*>(&Bs[0][brow][bc]) = rb[u];
    }
    __syncthreads();

    int buf = 0;
    #pragma unroll 1
    for (int kt = 0; kt < NN / 16; kt++) {
        if (kt + 1 < NN / 16) {
            const int koff = (kt + 1) * 16;
            #pragma unroll
            for (int u = 0; u < 2; u++) {
                int row = lrow0 + u * 64;
                ra[u] = *reinterpret_cast<const float4*>(A + (size_t)(m0 + row) * NN + koff + lc4);
                int brow = br0 + u * 8;
                rb[u] = *reinterpret_cast<const float4*>(Bp + (size_t)(koff + brow) * DD + n0 + bc);
            }
        }
        #pragma unroll
        for (int k = 0; k < 16; k++) {
            float4 a0 = *reinterpret_cast<const float4*>(&As[buf][k][ty * 8]);
            float4 a1 = *reinterpret_cast<const float4*>(&As[buf][k][ty * 8 + 4]);
            float4 b0 = *reinterpret_cast<const float4*>(&Bs[buf][k][tx * 8]);
            float4 b1 = *reinterpret_cast<const float4*>(&Bs[buf][k][tx * 8 + 4]);
            float av[8] = {a0.x, a0.y, a0.z, a0.w, a1.x, a1.y, a1.z, a1.w};
            float bv[8] = {b0.x, b0.y, b0.z, b0.w, b1.x, b1.y, b1.z, b1.w};
            #pragma unroll
            for (int i = 0; i < 8; i++)
                #pragma unroll
                for (int j = 0; j < 8; j++)
                    acc[i][j] = fmaf(av[i], bv[j], acc[i][j]);
        }
        if (kt + 1 < NN / 16) {
            int nb = buf ^ 1;
            #pragma unroll
            for (int u = 0; u < 2; u++) {
                int row = lrow0 + u * 64;
                As[nb][lc4 + 0][row] = ra[u].x; As[nb][lc4 + 1][row] = ra[u].y;
                As[nb][lc4 + 2][row] = ra[u].z; As[nb][lc4 + 3][row] = ra[u].w;
                int brow = br0 + u * 8;
                *reinterpret_cast<float4*>(&Bs[nb][brow][bc]) = rb[u];
            }
            __syncthreads();
            buf = nb;
        }
    }

    #pragma unroll
    for (int i = 0; i < 8; i++) {
        float4 o0 = make_float4(acc[i][0], acc[i][1], acc[i][2], acc[i][3]);
        float4 o1 = make_float4(acc[i][4], acc[i][5], acc[i][6], acc[i][7]);
        float* cp = C + (size_t)(m0 + ty * 8 + i) * DD + n0 + tx * 8;
        *reinterpret_cast<float4*>(cp)     = o0;
        *reinterpret_cast<float4*>(cp + 4) = o1;
    }
}

// ---------------------------------------------------------------------------
extern "C" void kernel_launch(void* const* d_in, const int* in_sizes, int n_in,
                              void* d_out, int out_size)
{
    (void)in_sizes; (void)n_in; (void)out_size;
    const float* cb = (const float*)d_in[0];   // codebook [16,1024,512]
    const float* pe = (const float*)d_in[1];   // patch_embed [16,4096,512]
    float* outp = (float*)d_out;               // [16,1024,512]

    dim3 blk(256);
    qk_kernel<<<dim3(NN / 128, KK / 128, BB), blk>>>(cb, pe);
    softmax_kernel<<<dim3(BB * KK), blk>>>();
    pv_kernel<<<dim3(DD / 128, KK / 128, BB), blk>>>(pe, outp);
}

// round 3
// speedup vs baseline: 1.2051x; 1.2051x over previous
#include <cuda_runtime.h>
#include <math.h>
#include <stdint.h>

#define BB 16
#define KK 1024
#define NN 4096
#define DD 512

#define BM 128
#define BN 256
#define BK 16

// scratch (allowed: __device__ globals)
__device__ float g_scores[(size_t)BB * KK * NN];   // 268 MB
__device__ float g_peT[(size_t)BB * DD * NN];      // 134 MB

// ------------------------------------------------------------------ utils ---
__device__ __forceinline__ uint32_t f2u(float x) { return __float_as_uint(x); }

__device__ __forceinline__ void tf32_split(float x, float& h, float& l) {
    uint32_t hu;
    asm("cvt.rna.tf32.f32 %0, %1;" : "=r"(hu) : "f"(x));
    h = __uint_as_float(hu);
    float r = x - h;
    uint32_t lu;
    asm("cvt.rna.tf32.f32 %0, %1;" : "=r"(lu) : "f"(r));
    l = __uint_as_float(lu);
}

#define MMA_TF32(d, a, b)                                                      \
    asm volatile(                                                              \
        "mma.sync.aligned.m16n8k8.row.col.f32.tf32.tf32.f32 "                  \
        "{%0,%1,%2,%3},{%4,%5,%6,%7},{%8,%9},{%0,%1,%2,%3};"                   \
        : "+f"((d)[0]), "+f"((d)[1]), "+f"((d)[2]), "+f"((d)[3])               \
        : "r"((a)[0]), "r"((a)[1]), "r"((a)[2]), "r"((a)[3]),                  \
          "r"((b)[0]), "r"((b)[1]))

// -------------------------------------------------- 3xTF32 mma.sync GEMM ----
// C[m,n] = sum_k A[m,k] * B[n,k]   (A: lda, B: ldb, both K-contiguous)
// Block 128x256, BK=16. 8 warps, each 64x64 warp tile (4 m-frags x 8 n-frags).
// smem per stage (floats): A: [kb2][t2][m128][pair4][2] = 4096
//                          B: [kb2][t2][n256][pair4][2] = 8192  -> 12288
__global__ __launch_bounds__(256, 1)
void gemm_tf32(const float* __restrict__ Ag, const float* __restrict__ Bg,
               float* __restrict__ Cg, int lda, int ldb, int ldc, int kdim,
               size_t sA, size_t sB, size_t sC)
{
    extern __shared__ float sm[];

    const int tid = threadIdx.x;
    const int lane = tid & 31;
    const int wid = tid >> 5;
    const int gid = lane >> 2;     // 0..7
    const int t4 = lane & 3;       // 0..3
    const int wm = (wid & 1) * 64;
    const int wn = (wid >> 1) * 64;
    const int m0 = blockIdx.y * BM;
    const int n0 = blockIdx.x * BN;

    const float* A = Ag + (size_t)blockIdx.z * sA;
    const float* B = Bg + (size_t)blockIdx.z * sB;
    float* C = Cg + (size_t)blockIdx.z * sC;

    // ---- loader unit setup: 3 units/thread (1 A half-row, 2 B half-rows) ----
    const float* gp[3];
    int smoff[3], tstr[3];
    #pragma unroll
    for (int u = 0; u < 3; u++) {
        int uu = tid + u * 256;
        if (uu < 256) {
            int m = uu >> 1, kb = uu & 1;
            gp[u] = A + (size_t)(m0 + m) * lda + kb * 8;
            smoff[u] = kb * 2048 + m * 8;
            tstr[u] = 1024;
        } else {
            int v = uu - 256;
            int n = v >> 1, kb = v & 1;
            gp[u] = B + (size_t)(n0 + n) * ldb + kb * 8;
            smoff[u] = 4096 + kb * 4096 + n * 8;
            tstr[u] = 2048;
        }
    }

    float acc[4][8][4];
    #pragma unroll
    for (int i = 0; i < 4; i++)
        #pragma unroll
        for (int j = 0; j < 8; j++)
            #pragma unroll
            for (int r = 0; r < 4; r++) acc[i][j][r] = 0.f;

    float4 pf[3][2];

    // prologue: chunk 0 -> stage 0
    #pragma unroll
    for (int u = 0; u < 3; u++) {
        pf[u][0] = *reinterpret_cast<const float4*>(gp[u]);
        pf[u][1] = *reinterpret_cast<const float4*>(gp[u] + 4);
    }
    #pragma unroll
    for (int u = 0; u < 3; u++) {
        float h[8], l[8];
        const float* v = &pf[u][0].x;
        #pragma unroll
        for (int e = 0; e < 8; e++) tf32_split(v[e], h[e], l[e]);
        float* d = sm + smoff[u];
        *reinterpret_cast<float4*>(d)     = make_float4(h[0], h[4], h[1], h[5]);
        *reinterpret_cast<float4*>(d + 4) = make_float4(h[2], h[6], h[3], h[7]);
        float* dl = d + tstr[u];
        *reinterpret_cast<float4*>(dl)     = make_float4(l[0], l[4], l[1], l[5]);
        *reinterpret_cast<float4*>(dl + 4) = make_float4(l[2], l[6], l[3], l[7]);
    }
    __syncthreads();

    const int NC = kdim / BK;
    #pragma unroll 1
    for (int c = 0; c < NC; c++) {
        const int s = c & 1;
        const float* sb = sm + s * 12288;

        if (c + 1 < NC) {
            #pragma unroll
            for (int u = 0; u < 3; u++) {
                const float* g = gp[u] + (size_t)(c + 1) * BK;
                pf[u][0] = *reinterpret_cast<const float4*>(g);
                pf[u][1] = *reinterpret_cast<const float4*>(g + 4);
            }
        }

        // ---- compute both k8 blocks of this stage ----
        #pragma unroll
        for (int kb = 0; kb < 2; kb++) {
            uint32_t a[2][4][4];
            uint32_t b[2][8][2];
            const float* Ab = sb + kb * 2048;
            const float* Bb = sb + 4096 + kb * 4096;
            #pragma unroll
            for (int t = 0; t < 2; t++) {
                #pragma unroll
                for (int i = 0; i < 4; i++) {
                    const float* pa = Ab + t * 1024 + (wm + i * 16 + gid) * 8 + t4 * 2;
                    float2 x = *reinterpret_cast<const float2*>(pa);
                    float2 y = *reinterpret_cast<const float2*>(pa + 64);
                    a[t][i][0] = f2u(x.x); a[t][i][2] = f2u(x.y);
                    a[t][i][1] = f2u(y.x); a[t][i][3] = f2u(y.y);
                }
                #pragma unroll
                for (int j = 0; j < 8; j++) {
                    const float* pb = Bb + t * 2048 + (wn + j * 8 + gid) * 8 + t4 * 2;
                    float2 x = *reinterpret_cast<const float2*>(pb);
                    b[t][j][0] = f2u(x.x); b[t][j][1] = f2u(x.y);
                }
            }
            #pragma unroll
            for (int i = 0; i < 4; i++)
                #pragma unroll
                for (int j = 0; j < 8; j++) {
                    MMA_TF32(acc[i][j], a[0][i], b[0][j]);   // hi*hi
                    MMA_TF32(acc[i][j], a[0][i], b[1][j]);   // hi*lo
                    MMA_TF32(acc[i][j], a[1][i], b[0][j]);   // lo*hi
                }
        }

        if (c + 1 < NC) {
            float* db = sm + (s ^ 1) * 12288;
            #pragma unroll
            for (int u = 0; u < 3; u++) {
                float h[8], l[8];
                const float* v = &pf[u][0].x;
                #pragma unroll
                for (int e = 0; e < 8; e++) tf32_split(v[e], h[e], l[e]);
                float* d = db + smoff[u];
                *reinterpret_cast<float4*>(d)     = make_float4(h[0], h[4], h[1], h[5]);
                *reinterpret_cast<float4*>(d + 4) = make_float4(h[2], h[6], h[3], h[7]);
                float* dl = d + tstr[u];
                *reinterpret_cast<float4*>(dl)     = make_float4(l[0], l[4], l[1], l[5]);
                *reinterpret_cast<float4*>(dl + 4) = make_float4(l[2], l[6], l[3], l[7]);
            }
        }
        __syncthreads();
    }

    // ---- epilogue ----
    #pragma unroll
    for (int i = 0; i < 4; i++) {
        int r = m0 + wm + i * 16 + gid;
        float* c0 = C + (size_t)r * ldc + n0 + wn + t4 * 2;
        float* c8 = c0 + (size_t)8 * ldc;
        #pragma unroll
        for (int j = 0; j < 8; j++) {
            *reinterpret_cast<float2*>(c0 + j * 8) = make_float2(acc[i][j][0], acc[i][j][1]);
            *reinterpret_cast<float2*>(c8 + j * 8) = make_float2(acc[i][j][2], acc[i][j][3]);
        }
    }
}

// ------------------------------------------------------------- transpose ----
__global__ __launch_bounds__(256)
void transpose_kernel(const float* __restrict__ pe, float* __restrict__ peT)
{
    __shared__ float t[32][33];
    const int b = blockIdx.z;
    const int n0 = blockIdx.x * 32, d0 = blockIdx.y * 32;
    const float* src = pe + (size_t)b * NN * DD;
    float* dst = peT + (size_t)b * DD * NN;
    #pragma unroll
    for (int i = threadIdx.y; i < 32; i += 8)
        t[i][threadIdx.x] = src[(size_t)(n0 + i) * DD + d0 + threadIdx.x];
    __syncthreads();
    #pragma unroll
    for (int i = threadIdx.y; i < 32; i += 8)
        dst[(size_t)(d0 + i) * NN + n0 + threadIdx.x] = t[threadIdx.x][i];
}

// ---------------------------------------------------------------- softmax ---
__device__ __forceinline__ float fast_exp(float x) {
    x = fmaxf(x, -87.0f);
    float t = x * 1.4426950408889634f;
    float n = rintf(t);
    float r = fmaf(n, -0.693145751953125f, x);
    r = fmaf(n, -1.428606765330187e-06f, r);
    float p = 1.38888892e-3f;
    p = fmaf(p, r, 8.33333377e-3f);
    p = fmaf(p, r, 4.16666679e-2f);
    p = fmaf(p, r, 1.66666672e-1f);
    p = fmaf(p, r, 0.5f);
    p = fmaf(p, r, 1.0f);
    p = fmaf(p, r, 1.0f);
    float s = __int_as_float(((int)n + 127) << 23);
    return p * s;
}

__global__ __launch_bounds__(256)
void softmax_kernel()
{
    float* p = g_scores + (size_t)blockIdx.x * NN;
    const int tid = threadIdx.x;
    __shared__ float red[8];

    float4 v[4];
    float m = -3.4e38f;
    #pragma unroll
    for (int i = 0; i < 4; i++) {
        v[i] = reinterpret_cast<float4*>(p)[tid + i * 256];
        m = fmaxf(m, fmaxf(fmaxf(v[i].x, v[i].y), fmaxf(v[i].z, v[i].w)));
    }
    #pragma unroll
    for (int o = 16; o > 0; o >>= 1) m = fmaxf(m, __shfl_xor_sync(0xffffffffu, m, o));
    if ((tid & 31) == 0) red[tid >> 5] = m;
    __syncthreads();
    m = red[0];
    #pragma unroll
    for (int w = 1; w < 8; w++) m = fmaxf(m, red[w]);
    __syncthreads();

    float s = 0.f;
    #pragma unroll
    for (int i = 0; i < 4; i++) {
        v[i].x = fast_exp(v[i].x - m);
        v[i].y = fast_exp(v[i].y - m);
        v[i].z = fast_exp(v[i].z - m);
        v[i].w = fast_exp(v[i].w - m);
        s += (v[i].x + v[i].y) + (v[i].z + v[i].w);
    }
    #pragma unroll
    for (int o = 16; o > 0; o >>= 1) s += __shfl_xor_sync(0xffffffffu, s, o);
    if ((tid & 31) == 0) red[tid >> 5] = s;
    __syncthreads();
    s = ((red[0] + red[1]) + (red[2] + red[3])) + ((red[4] + red[5]) + (red[6] + red[7]));

    const float inv = 1.0f / s;
    #pragma unroll
    for (int i = 0; i < 4; i++) {
        v[i].x *= inv; v[i].y *= inv; v[i].z *= inv; v[i].w *= inv;
        reinterpret_cast<float4*>(p)[tid + i * 256] = v[i];
    }
}

// ---------------------------------------------------------------------------
extern "C" void kernel_launch(void* const* d_in, const int* in_sizes, int n_in,
                              void* d_out, int out_size)
{
    (void)in_sizes; (void)n_in; (void)out_size;
    const float* cb = (const float*)d_in[0];   // codebook [16,1024,512]
    const float* pe = (const float*)d_in[1];   // patch_embed [16,4096,512]
    float* outp = (float*)d_out;               // [16,1024,512]

    float* scores = nullptr;
    float* peT = nullptr;
    cudaGetSymbolAddress((void**)&scores, g_scores);
    cudaGetSymbolAddress((void**)&peT, g_peT);

    const int DYN = 2 * 12288 * sizeof(float);  // 96 KB
    cudaFuncSetAttribute(gemm_tf32, cudaFuncAttributeMaxDynamicSharedMemorySize, DYN);

    transpose_kernel<<<dim3(NN / 32, DD / 32, BB), dim3(32, 8)>>>(pe, peT);

    // scores[b,k,n] = sum_d cb[b,k,d] * pe[b,n,d]
    gemm_tf32<<<dim3(NN / BN, KK / BM, BB), 256, DYN>>>(
        cb, pe, scores, DD, DD, NN, DD,
        (size_t)KK * DD, (size_t)NN * DD, (size_t)KK * NN);

    softmax_kernel<<<dim3(BB * KK), 256>>>();

    // out[b,k,d] = sum_n attn[b,k,n] * peT[b,d,n]
    gemm_tf32<<<dim3(DD / BN, KK / BM, BB), 256, DYN>>>(
        scores, peT, outp, NN, NN, DD, NN,
        (size_t)KK * NN, (size_t)DD * NN, (size_t)KK * DD);
}